// round 3
// baseline (speedup 1.0000x reference)
#include <cuda_runtime.h>

// out = clip(x + laplace * mask, 0, 1), elementwise over 38,535,168 fp32.
// Pure HBM-streaming kernel: 3 reads + 1 write, vectorized 128-bit.

__global__ void rrn_clip_kernel(const float4* __restrict__ x,
                                const float4* __restrict__ lap,
                                const float4* __restrict__ mask,
                                float4* __restrict__ out,
                                int n4) {
    int i = blockIdx.x * blockDim.x + threadIdx.x;
    if (i >= n4) return;
    float4 xv = x[i];
    float4 lv = lap[i];
    float4 mv = mask[i];
    float4 r;
    r.x = __saturatef(fmaf(lv.x, mv.x, xv.x));
    r.y = __saturatef(fmaf(lv.y, mv.y, xv.y));
    r.z = __saturatef(fmaf(lv.z, mv.z, xv.z));
    r.w = __saturatef(fmaf(lv.w, mv.w, xv.w));
    out[i] = r;
}

// Tail handler for n not divisible by 4 (not needed for this shape, but safe).
__global__ void rrn_clip_tail(const float* __restrict__ x,
                              const float* __restrict__ lap,
                              const float* __restrict__ mask,
                              float* __restrict__ out,
                              int start, int n) {
    int i = start + blockIdx.x * blockDim.x + threadIdx.x;
    if (i >= n) return;
    out[i] = __saturatef(fmaf(lap[i], mask[i], x[i]));
}

extern "C" void kernel_launch(void* const* d_in, const int* in_sizes, int n_in,
                              void* d_out, int out_size) {
    // metadata order: x, eps (dead scalar), laplace_noise, mask
    const float* x    = (const float*)d_in[0];
    const float* lap  = (const float*)d_in[2];
    const float* mask = (const float*)d_in[3];
    float* out        = (float*)d_out;

    int n  = in_sizes[0];
    int n4 = n >> 2;

    if (n4 > 0) {
        int threads = 256;
        int blocks = (n4 + threads - 1) / threads;
        rrn_clip_kernel<<<blocks, threads>>>(
            (const float4*)x, (const float4*)lap, (const float4*)mask,
            (float4*)out, n4);
    }
    int tail_start = n4 << 2;
    int tail = n - tail_start;
    if (tail > 0) {
        rrn_clip_tail<<<1, 32>>>(x, lap, mask, out, tail_start, n);
    }
}

// round 4
// speedup vs baseline: 1.0029x; 1.0029x over previous
#include <cuda_runtime.h>

// out = clip(x + laplace * mask, 0, 1), elementwise, 38,535,168 fp32.
// HBM-roofline streaming kernel: 3 reads + 1 write, 616.6 MB irreducible.
// R3: non-temporal (.cs) loads/stores + 2x float4 per thread (front-batched
// LDGs for MLP_p1=6), halved block count.

#define VPT 2  // float4s per thread

__global__ void rrn_clip_kernel(const float4* __restrict__ x,
                                const float4* __restrict__ lap,
                                const float4* __restrict__ mask,
                                float4* __restrict__ out,
                                int n4) {
    int base = (blockIdx.x * blockDim.x) * VPT + threadIdx.x;

    float4 xv[VPT], lv[VPT], mv[VPT];
    // Front-batch all loads (streaming, evict-first)
    #pragma unroll
    for (int j = 0; j < VPT; j++) {
        int i = base + j * blockDim.x;
        if (i < n4) {
            xv[j] = __ldcs(x + i);
            lv[j] = __ldcs(lap + i);
            mv[j] = __ldcs(mask + i);
        }
    }
    #pragma unroll
    for (int j = 0; j < VPT; j++) {
        int i = base + j * blockDim.x;
        if (i < n4) {
            float4 r;
            r.x = __saturatef(fmaf(lv[j].x, mv[j].x, xv[j].x));
            r.y = __saturatef(fmaf(lv[j].y, mv[j].y, xv[j].y));
            r.z = __saturatef(fmaf(lv[j].z, mv[j].z, xv[j].z));
            r.w = __saturatef(fmaf(lv[j].w, mv[j].w, xv[j].w));
            __stcs(out + i, r);
        }
    }
}

// Scalar tail for n not divisible by 4 (not hit for this shape).
__global__ void rrn_clip_tail(const float* __restrict__ x,
                              const float* __restrict__ lap,
                              const float* __restrict__ mask,
                              float* __restrict__ out,
                              int start, int n) {
    int i = start + blockIdx.x * blockDim.x + threadIdx.x;
    if (i >= n) return;
    out[i] = __saturatef(fmaf(__ldcs(lap + i), __ldcs(mask + i), __ldcs(x + i)));
}

extern "C" void kernel_launch(void* const* d_in, const int* in_sizes, int n_in,
                              void* d_out, int out_size) {
    // metadata order: x, eps (dead scalar), laplace_noise, mask
    const float* x    = (const float*)d_in[0];
    const float* lap  = (const float*)d_in[2];
    const float* mask = (const float*)d_in[3];
    float* out        = (float*)d_out;

    int n  = in_sizes[0];
    int n4 = n >> 2;

    if (n4 > 0) {
        const int threads = 256;
        int blocks = (n4 + threads * VPT - 1) / (threads * VPT);
        rrn_clip_kernel<<<blocks, threads>>>(
            (const float4*)x, (const float4*)lap, (const float4*)mask,
            (float4*)out, n4);
    }
    int tail_start = n4 << 2;
    if (n - tail_start > 0) {
        rrn_clip_tail<<<1, 32>>>(x, lap, mask, out, tail_start, n);
    }
}